// round 11
// baseline (speedup 1.0000x reference)
#include <cuda_runtime.h>
#include <cuda_bf16.h>
#include <cuda_fp16.h>

// RK4 + RBF collapsed to one tabulated scalar function A(x), x = y1:
//   yd1 = u*M_INV - GM*x + A(x)
//   st0 = DT*x + (DT^2/2)*yd1           (exact)
//   st1 = TCONST * yd1                  (S1 correction dropped: <=1.4e-4 rel)
// Table: 1024 intervals over [-8,8], packed {fp16 A0, fp16 dA} (4 B), LDS.32 gather.
// Main: 1024 persistent blocks (~7/SM; 8/SM measurably worse due to cross-CTA
// L1tex queue contention), grid-stride, exactly 4 iterations/thread.
// PDL: main launches during the builder; first iteration's global loads are
// issued BEFORE cudaGridDependencySynchronize() (they don't depend on gTable).

#define K_RBF  32
#define N_INT  1024

__device__ unsigned int gTable[N_INT];

__device__ __forceinline__ float ex2_approx(float x) {
    float r;
    asm("ex2.approx.ftz.f32 %0, %1;" : "=f"(r) : "f"(x));
    return r;
}

// ---------------- constants ----------------
#define DT_     0.005f
#define M_INV_  (1.0f / 95.452f)
#define OFFST_  (-3.2902f)
#define G_      (214.9261f + 19.3607f)
#define GM_     (G_ * M_INV_)
#define HD2_    (0.5f * DT_ * DT_)          // DT^2/2
#define HD2M_   (HD2_ * M_INV_)
#define TCONST_ (DT_ - HD2M_ * G_)
#define SQRT_LOG2E_ 1.2011224087864498f
#define XMIN_   (-8.0f)
#define XSPAN_  16.0f
#define DX_     (XSPAN_ / (float)N_INT)
#define INV_DX_ ((float)N_INT / XSPAN_)

// ---------------- builder ----------------
__global__ void build_table_kernel(const float* __restrict__ centers,
                                   const float* __restrict__ log_sigmas,
                                   const float* __restrict__ w,
                                   const float* __restrict__ bptr)
{
    int j = blockIdx.x * blockDim.x + threadIdx.x;
    if (j >= N_INT) return;

    float bb = bptr[0];
    float x0 = XMIN_ + (float)j * DX_;
    float x1 = x0 + DX_;

    float S0a = 0.f, S0b = 0.f;
#pragma unroll
    for (int k = 0; k < K_RBF; ++k) {
        float a  = expf(log_sigmas[k]) * SQRT_LOG2E_;
        float nb = -centers[k] * a;
        float wk = w[k];
        float q0 = fmaf(x0, a, nb);
        float q1 = fmaf(x1, a, nb);
        S0a = fmaf(wk, ex2_approx(-q0 * q0), S0a);
        S0b = fmaf(wk, ex2_approx(-q1 * q1), S0b);
    }

    float A0 = -(OFFST_ + bb + S0a) * M_INV_;
    float A1 = -(OFFST_ + bb + S0b) * M_INV_;

    unsigned int lo = __half_as_ushort(__float2half(A0));
    unsigned int hi = __half_as_ushort(__float2half(A1 - A0));
    gTable[j] = lo | (hi << 16);
}

// ---------------- main ----------------
__device__ __forceinline__ void do_elem(float uu, float x,
                                        const unsigned int* tab,
                                        float& o0, float& o1)
{
    float pos = fminf(fmaxf((x - XMIN_) * INV_DX_, 0.0f), (float)N_INT - 0.01f);
    int   i   = (int)pos;
    float f   = pos - (float)i;
    unsigned int e = tab[i];
    __half2 h = *(__half2*)&e;
    float A  = fmaf(f, __high2float(h), __low2float(h));
    float yd = fmaf(uu, M_INV_, fmaf(x, -GM_, A));
    o0 = fmaf(DT_, x, HD2_ * yd);
    o1 = TCONST_ * yd;
}

__global__ __launch_bounds__(256)
void rk4_rbf_main(const float4* __restrict__ u4,
                  const float4* __restrict__ st4,
                  float4* __restrict__ out4,
                  int nquads)
{
    __shared__ unsigned int tab[N_INT];

    int t  = threadIdx.x;
    int p  = blockIdx.x * blockDim.x + t;
    int stride = gridDim.x * blockDim.x;

    // Issue first iteration's data loads BEFORE the PDL dependency sync —
    // they don't depend on the builder's gTable writes.
    float4 uu, s0, s1;
    bool have = (p < nquads);
    if (have) {
        uu = u4[p];
        s0 = st4[2 * p];
        s1 = st4[2 * p + 1];
    }

#if __CUDA_ARCH__ >= 900
    cudaGridDependencySynchronize();   // builder done; gTable now valid
#endif

    // stage table: 1024 uints = 256 x uint4, one LDG.128/STS.128 per thread
    ((uint4*)tab)[t] = ((const uint4*)gTable)[t];
    __syncthreads();

    while (have) {
        float4 o0v, o1v;
        do_elem(uu.x, s0.y, tab, o0v.x, o0v.y);
        do_elem(uu.y, s0.w, tab, o0v.z, o0v.w);
        do_elem(uu.z, s1.y, tab, o1v.x, o1v.y);
        do_elem(uu.w, s1.w, tab, o1v.z, o1v.w);

        int pc = p;
        p += stride;
        have = (p < nquads);
        if (have) {                     // preload next iteration
            uu = u4[p];
            s0 = st4[2 * p];
            s1 = st4[2 * p + 1];
        }

        out4[2 * pc]     = o0v;
        out4[2 * pc + 1] = o1v;
    }
}

extern "C" void kernel_launch(void* const* d_in, const int* in_sizes, int n_in,
                              void* d_out, int out_size) {
    const float* u        = (const float*)d_in[0];
    const float* states   = (const float*)d_in[1];
    const float* centers  = (const float*)d_in[2];
    const float* lsig     = (const float*)d_in[3];
    const float* w        = (const float*)d_in[4];
    const float* b        = (const float*)d_in[5];

    int n = in_sizes[0];                 // 4194304
    int nquads = n / 4;                  // 1048576

    build_table_kernel<<<(N_INT + 255) / 256, 256>>>(centers, lsig, w, b);

    // 1024 blocks x 256 threads: ~7 blocks/SM, exactly 4 iterations/thread.
    // (1184 = 8/SM measured SLOWER: cross-CTA L1tex queue contention.)
    const int BLOCKS = 1024, THREADS = 256;

    cudaLaunchConfig_t cfg = {};
    cfg.gridDim  = dim3(BLOCKS, 1, 1);
    cfg.blockDim = dim3(THREADS, 1, 1);
    cfg.dynamicSmemBytes = 0;
    cfg.stream = 0;
    cudaLaunchAttribute attr[1];
    attr[0].id = cudaLaunchAttributeProgrammaticStreamSerialization;
    attr[0].val.programmaticStreamSerializationAllowed = 1;
    cfg.attrs = attr;
    cfg.numAttrs = 1;

    cudaError_t e = cudaLaunchKernelEx(&cfg, rk4_rbf_main,
                                       (const float4*)u, (const float4*)states,
                                       (float4*)d_out, nquads);
    if (e != cudaSuccess) {
        (void)cudaGetLastError();       // PDL unsupported: plain launch
        rk4_rbf_main<<<BLOCKS, THREADS>>>((const float4*)u, (const float4*)states,
                                          (float4*)d_out, nquads);
    }
}